// round 11
// baseline (speedup 1.0000x reference)
#include <cuda_runtime.h>
#include <cuda_bf16.h>
#include <cstdint>

#define B_ 256
#define T_ 256
#define F_ 512
#define H_ 1024
#define A_ 1000

// recurrence: 128 blocks = 2 row-groups(128) x 8 col-groups(128) x 8 k-splits(128)
#define NBLK 128
#define RTHREADS 512
#define RROWS 128
#define RCOLS 128
#define RK    128
#define NSPLIT 8
#define BKr   64
#define SPAD  142   // staging row pitch in u64 (EVEN for LDS.128 alignment)

// sigma-swizzle for staged A rows: disjoint bank-quads for the 8 row-groups
__device__ __forceinline__ int sigm(int m) { return m + 2 * (m >> 4); }

// ---------------- scratch (static device globals; no allocation) -------------
__device__ float g_xw[(size_t)B_ * T_ * H_];     // input projection [B][T][H]
__device__ float g_hbuf[B_ * H_];                // hidden state
__device__ float g_part[NSPLIT][B_ * H_];        // k-split partials [q][m][n]
__device__ float g_hid[B_ * H_];
__device__ float g_logits[B_ * A_];
__device__ int   g_action[B_];
__device__ float g_rowloss[B_];

// grid barrier state (self-cleaning; safe across graph replays)
__device__ unsigned g_cnt = 0;
__device__ volatile unsigned g_gen = 0;

// ---------------- packed fp32x2 FMA helpers (Blackwell) ----------------------
__device__ __forceinline__ unsigned long long pack2(float lo, float hi) {
    unsigned long long r;
    asm("mov.b64 %0, {%1, %2};" : "=l"(r) : "f"(lo), "f"(hi));
    return r;
}
__device__ __forceinline__ void unpack2(unsigned long long v, float& lo, float& hi) {
    asm("mov.b64 {%0, %1}, %2;" : "=f"(lo), "=f"(hi) : "l"(v));
}
__device__ __forceinline__ void ffma2(unsigned long long& d, unsigned long long a,
                                      unsigned long long b) {
    asm("fma.rn.f32x2 %0, %1, %2, %0;" : "+l"(d) : "l"(a), "l"(b));
}

// ---------------- grid-wide barrier ------------------------------------------
__device__ __forceinline__ void grid_sync() {
    __syncthreads();
    if (threadIdx.x == 0) {
        __threadfence();
        unsigned gen = g_gen;
        unsigned old = atomicAdd(&g_cnt, 1u);
        if (old == NBLK - 1) {
            g_cnt = 0;
            __threadfence();
            g_gen = gen + 1;
        } else {
            while (g_gen == gen) { }
            __threadfence();
        }
    }
    __syncthreads();
}

// ---------------- persistent recurrence kernel -------------------------------
// Block (r,c,q): rows [r*128,+128), cols [c*128,+128), k in [q*128,+128).
// Slab W[k-range][col-range] (64 KB) resident in smem for all steps.
// Warps in 4x4 grid: warp (wr,wc) owns rows wr*32..+31, cols wc*32..+31.
// Lane: rg=lane>>2 (4-row group), cg=lane&3 (8-col group). Thread = 4x8 tile.
// Per kk per warp: 2 LDS.128 A (sigma-swizzled, conflict-free) +
// 2 LDS.128 B (bank-quad disjoint, 8-way bcast) + 16 FFMA2
// -> 64 crossbar phases/kk/SM vs 128 FFMA2 cyc/kk: crossbar at 50%.

struct RecurSmem {
    float Whs[RK * RCOLS];                       // 64 KB slab
    unsigned long long hsd[2 * BKr * SPAD];      // 142 KB staging (dup'd pairs)
};

__device__ __forceinline__ void stage_store(
    unsigned long long* __restrict__ hsd, int bufk0, int ko, int scol,
    const float4 v[4])
{
#pragma unroll
    for (int j = 0; j < 4; ++j) {
        const int kl = bufk0 + ko + 16 * j;
        unsigned long long* d = &hsd[(size_t)kl * SPAD + scol];
        d[0 * SPAD] = pack2(v[j].x, v[j].x);
        d[1 * SPAD] = pack2(v[j].y, v[j].y);
        d[2 * SPAD] = pack2(v[j].z, v[j].z);
        d[3 * SPAD] = pack2(v[j].w, v[j].w);
    }
}

// one 64-kk chunk: asb = thread's A base (sigma'd), ws = thread's B base
__device__ __forceinline__ void compute_chunk(
    const unsigned long long* __restrict__ asb,
    const float* __restrict__ ws,
    unsigned long long acc[4][4])
{
#pragma unroll 16
    for (int kk = 0; kk < BKr; ++kk) {
        ulonglong2 a01 = *(const ulonglong2*)(asb + (size_t)kk * SPAD);      // rows 0,1
        ulonglong2 a23 = *(const ulonglong2*)(asb + (size_t)kk * SPAD + 2);  // rows 2,3
        ulonglong2 b01 = *(const ulonglong2*)(ws + (size_t)kk * RCOLS);      // colpairs 0,1
        ulonglong2 b23 = *(const ulonglong2*)(ws + (size_t)kk * RCOLS + 4);  // colpairs 2,3
        ffma2(acc[0][0], a01.x, b01.x); ffma2(acc[0][1], a01.x, b01.y);
        ffma2(acc[0][2], a01.x, b23.x); ffma2(acc[0][3], a01.x, b23.y);
        ffma2(acc[1][0], a01.y, b01.x); ffma2(acc[1][1], a01.y, b01.y);
        ffma2(acc[1][2], a01.y, b23.x); ffma2(acc[1][3], a01.y, b23.y);
        ffma2(acc[2][0], a23.x, b01.x); ffma2(acc[2][1], a23.x, b01.y);
        ffma2(acc[2][2], a23.x, b23.x); ffma2(acc[2][3], a23.x, b23.y);
        ffma2(acc[3][0], a23.y, b01.x); ffma2(acc[3][1], a23.y, b01.y);
        ffma2(acc[3][2], a23.y, b23.x); ffma2(acc[3][3], a23.y, b23.y);
    }
}

__device__ __forceinline__ void tile_gemm_part(
    const float* __restrict__ hrow,      // &h[(bm+m_l)*H_ + bk + ko]
    const float* __restrict__ Whs,
    unsigned long long* __restrict__ hsd,
    int arow_sig, int bcol, int scol, int ko,
    unsigned long long acc[4][4])
{
    float4 v[4];
#pragma unroll
    for (int j = 0; j < 4; ++j)
        v[j] = __ldcg((const float4*)(hrow + 16 * j));
    stage_store(hsd, 0, ko, scol, v);
    __syncthreads();

    // prefetch chunk 1 while computing chunk 0
#pragma unroll
    for (int j = 0; j < 4; ++j)
        v[j] = __ldcg((const float4*)(hrow + BKr + 16 * j));

    compute_chunk(&hsd[arow_sig], &Whs[bcol], acc);

    stage_store(hsd, BKr, ko, scol, v);
    __syncthreads();

    compute_chunk(&hsd[(size_t)BKr * SPAD + arow_sig],
                  &Whs[(size_t)BKr * RCOLS + bcol], acc);
}

__device__ __forceinline__ void store_partials(
    unsigned long long acc[4][4], float* __restrict__ pq,
    int bm, int bn, int wr, int wc, int rg, int cg)
{
#pragma unroll
    for (int i = 0; i < 4; ++i) {
        const int m = bm + wr * 32 + rg * 4 + i;
        float* prow = &pq[(long)m * H_ + bn + wc * 32 + cg * 8];
        float v0, v1, v2, v3, v4, v5, v6, v7;
        unpack2(acc[i][0], v0, v1);
        unpack2(acc[i][1], v2, v3);
        unpack2(acc[i][2], v4, v5);
        unpack2(acc[i][3], v6, v7);
        __stcg((float4*)prow,       make_float4(v0, v1, v2, v3));
        __stcg((float4*)(prow + 4), make_float4(v4, v5, v6, v7));
    }
}

__global__ void __launch_bounds__(RTHREADS, 1)
rnn_recur(const float* __restrict__ xw, const float* __restrict__ Wh,
          const float* __restrict__ W1, const float* __restrict__ b1,
          float* __restrict__ h, float* __restrict__ hid)
{
    extern __shared__ __align__(16) char smraw[];
    RecurSmem* sm = (RecurSmem*)smraw;

    const int tid = threadIdx.x;
    const int bid = blockIdx.x;
    const int q = bid & 7;
    const int c = (bid >> 3) & 7;
    const int r = bid >> 6;
    const int bm = r * RROWS, bn = c * RCOLS, bk = q * RK;

    // compute-phase thread mapping (4x4 warp grid, 4x8 thread tile)
    const int w  = tid >> 5;
    const int wr = w >> 2, wc = w & 3;
    const int lane = tid & 31;
    const int rg = lane >> 2, cg = lane & 3;
    const int arow_sig = sigm(wr * 32 + rg * 4);         // A base (u64, sigma'd)
    const int bcol = wc * 32 + cg * 8;                   // B base (floats)

    // staging-phase mapping
    const int m_l = tid >> 2;        // 0..127
    const int ko  = (tid & 3) * 4;   // {0,4,8,12}
    const int scol = sigm(m_l);

    const int gtid = bid * RTHREADS + tid;
    const int rm = gtid >> 8;
    const int rn4 = (gtid & 255) * 4;
    const long roff = (long)rm * H_ + rn4;

    // load Wh slab [bk..bk+128) x [bn..bn+128) (resident all steps)
    for (int v = tid; v < RK * RCOLS / 4; v += RTHREADS) {
        int k = v >> 5, nq = v & 31;
        float4 wv = __ldg((const float4*)&Wh[(long)(bk + k) * H_ + bn + nq * 4]);
        *(float4*)&sm->Whs[k * RCOLS + nq * 4] = wv;
    }

    {
        float4 v = __ldg((const float4*)&xw[((long)rm * T_ + 0) * H_ + rn4]);
        v.x = fmaxf(v.x, 0.f); v.y = fmaxf(v.y, 0.f);
        v.z = fmaxf(v.z, 0.f); v.w = fmaxf(v.w, 0.f);
        __stcg((float4*)&h[roff], v);
    }
    grid_sync();

    for (int t = 1; t < T_; ++t) {
        float4 xv = __ldcg((const float4*)&xw[((long)rm * T_ + t) * H_ + rn4]);

        unsigned long long acc[4][4];
#pragma unroll
        for (int i = 0; i < 4; ++i)
#pragma unroll
            for (int j = 0; j < 4; ++j) acc[i][j] = 0ull;

        tile_gemm_part(&h[(long)(bm + m_l) * H_ + bk + ko], sm->Whs, sm->hsd,
                       arow_sig, bcol, scol, ko, acc);
        store_partials(acc, g_part[q], bm, bn, wr, wc, rg, cg);
        grid_sync();

        // reduce: h = relu(xw[:,t,:] + sum_q partial_q)
        {
            float4 s = xv;
#pragma unroll
            for (int qq = 0; qq < NSPLIT; ++qq) {
                float4 p = __ldcg((const float4*)&g_part[qq][roff]);
                s.x += p.x; s.y += p.y; s.z += p.z; s.w += p.w;
            }
            s.x = fmaxf(s.x, 0.f); s.y = fmaxf(s.y, 0.f);
            s.z = fmaxf(s.z, 0.f); s.w = fmaxf(s.w, 0.f);
            __stcg((float4*)&h[roff], s);
        }
        grid_sync();
    }
    // h now holds h_last (h_256)

    // fused dense1: hid = relu(h_last @ W1 + b1) — swap slab to W1
    for (int v = tid; v < RK * RCOLS / 4; v += RTHREADS) {
        int k = v >> 5, nq = v & 31;
        float4 wv = __ldg((const float4*)&W1[(long)(bk + k) * H_ + bn + nq * 4]);
        *(float4*)&sm->Whs[k * RCOLS + nq * 4] = wv;
    }
    __syncthreads();
    {
        unsigned long long acc[4][4];
#pragma unroll
        for (int i = 0; i < 4; ++i)
#pragma unroll
            for (int j = 0; j < 4; ++j) acc[i][j] = 0ull;
        tile_gemm_part(&h[(long)(bm + m_l) * H_ + bk + ko], sm->Whs, sm->hsd,
                       arow_sig, bcol, scol, ko, acc);
        store_partials(acc, g_part[q], bm, bn, wr, wc, rg, cg);
        grid_sync();
        {
            float4 s = __ldg((const float4*)&b1[rn4]);
#pragma unroll
            for (int qq = 0; qq < NSPLIT; ++qq) {
                float4 p = __ldcg((const float4*)&g_part[qq][roff]);
                s.x += p.x; s.y += p.y; s.z += p.z; s.w += p.w;
            }
            s.x = fmaxf(s.x, 0.f); s.y = fmaxf(s.y, 0.f);
            s.z = fmaxf(s.z, 0.f); s.w = fmaxf(s.w, 0.f);
            __stcg((float4*)&hid[roff], s);
        }
    }
}

// ---------------- double-buffered SGEMM template (dup-A) ---------------------
template <int BM, int BN, int BK, int TM, int TN, int THREADS, bool RELU>
__global__ void __launch_bounds__(THREADS)
sgemm_kernel(int M, int N, int K,
             const float* __restrict__ A, int lda,
             const float* __restrict__ Bm, int ldb,
             const float* __restrict__ bias,
             float* __restrict__ C, int ldc)
{
    static_assert(TN % 4 == 0 && TM % 2 == 0, "");
    constexpr int TX = BN / TN;
    constexpr int TY = BM / TM;
    static_assert(TX * TY == THREADS, "");

    __shared__ __align__(16) unsigned long long As[2][BK][BM];
    __shared__ __align__(16) float Bs[2][BK][BN];

    const int tid = threadIdx.x;
    const int tx  = tid % TX;
    const int ty  = tid / TX;
    const int bm  = blockIdx.y * BM;
    const int bn  = blockIdx.x * BN;

    constexpr int A_VECS = BM * BK / 4;
    constexpr int A_PER  = A_VECS / THREADS;
    constexpr int B_VECS = BK * BN / 4;
    constexpr int B_PER  = B_VECS / THREADS;
    static_assert(A_VECS % THREADS == 0 && B_VECS % THREADS == 0, "");

    float4 aReg[A_PER];
    float4 bReg[B_PER];

    auto loadA = [&](int k0) {
#pragma unroll
        for (int i = 0; i < A_PER; ++i) {
            int v   = tid + i * THREADS;
            int row = v / (BK / 4);
            int kc  = (v % (BK / 4)) * 4;
            aReg[i] = *reinterpret_cast<const float4*>(
                &A[(long)(bm + row) * lda + k0 + kc]);
        }
    };
    auto loadB = [&](int k0) {
#pragma unroll
        for (int i = 0; i < B_PER; ++i) {
            int v    = tid + i * THREADS;
            int krow = v / (BN / 4);
            int nc   = (v % (BN / 4)) * 4;
            int col  = bn + nc;
            if (col < N)
                bReg[i] = *reinterpret_cast<const float4*>(
                    &Bm[(long)(k0 + krow) * ldb + col]);
            else
                bReg[i] = make_float4(0.f, 0.f, 0.f, 0.f);
        }
    };
    auto storeA = [&](int buf) {
#pragma unroll
        for (int i = 0; i < A_PER; ++i) {
            int v   = tid + i * THREADS;
            int row = v / (BK / 4);
            int kc  = (v % (BK / 4)) * 4;
            As[buf][kc + 0][row] = pack2(aReg[i].x, aReg[i].x);
            As[buf][kc + 1][row] = pack2(aReg[i].y, aReg[i].y);
            As[buf][kc + 2][row] = pack2(aReg[i].z, aReg[i].z);
            As[buf][kc + 3][row] = pack2(aReg[i].w, aReg[i].w);
        }
    };
    auto storeB = [&](int buf) {
#pragma unroll
        for (int i = 0; i < B_PER; ++i) {
            int v    = tid + i * THREADS;
            int krow = v / (BN / 4);
            int nc   = (v % (BN / 4)) * 4;
            *reinterpret_cast<float4*>(&Bs[buf][krow][nc]) = bReg[i];
        }
    };

    unsigned long long acc[TM][TN / 2];
#pragma unroll
    for (int i = 0; i < TM; ++i)
#pragma unroll
        for (int j = 0; j < TN / 2; ++j) acc[i][j] = 0ull;

    loadA(0); loadB(0);
    storeA(0); storeB(0);
    __syncthreads();

    const int nTiles = K / BK;
    for (int kt = 0; kt < nTiles; ++kt) {
        const int cur = kt & 1, nxt = cur ^ 1;
        if (kt + 1 < nTiles) { loadA((kt + 1) * BK); loadB((kt + 1) * BK); }

#pragma unroll
        for (int kk = 0; kk < BK; ++kk) {
            unsigned long long a2[TM];
#pragma unroll
            for (int i = 0; i < TM; i += 2) {
                ulonglong2 t = *reinterpret_cast<const ulonglong2*>(
                    &As[cur][kk][ty * TM + i]);
                a2[i] = t.x; a2[i + 1] = t.y;
            }
            unsigned long long b2[TN / 2];
#pragma unroll
            for (int j = 0; j < TN / 4; ++j) {
                ulonglong2 bv = *reinterpret_cast<const ulonglong2*>(
                    &Bs[cur][kk][tx * TN + 4 * j]);
                b2[2 * j] = bv.x; b2[2 * j + 1] = bv.y;
            }
#pragma unroll
            for (int i = 0; i < TM; ++i)
#pragma unroll
                for (int j = 0; j < TN / 2; ++j) ffma2(acc[i][j], a2[i], b2[j]);
        }

        if (kt + 1 < nTiles) { storeA(nxt); storeB(nxt); }
        __syncthreads();
    }

#pragma unroll
    for (int i = 0; i < TM; ++i) {
        const int m = bm + ty * TM + i;
#pragma unroll
        for (int j = 0; j < TN / 2; ++j) {
            float lo, hi;
            unpack2(acc[i][j], lo, hi);
            float v[2] = {lo, hi};
            const int n0 = bn + tx * TN + 2 * j;
#pragma unroll
            for (int e = 0; e < 2; ++e) {
                const int n = n0 + e;
                if (n < N) {
                    float cv = v[e];
                    if (bias) cv += bias[n];
                    if (RELU) cv = fmaxf(cv, 0.0f);
                    C[(long)m * ldc + n] = cv;
                }
            }
        }
    }
}

// ---------------- threefry2x32 / JAX gumbel ----------------------------------
__device__ __forceinline__ float gumbel_at(uint32_t idx) {
    const uint32_t k0 = 0u, k1 = 42u;
    const uint32_t ks2 = k0 ^ k1 ^ 0x1BD11BDAu;
    uint32_t x0 = k0;
    uint32_t x1 = idx + k1;
#define RND(r) { x0 += x1; x1 = ((x1 << (r)) | (x1 >> (32 - (r)))) ^ x0; }
    RND(13) RND(15) RND(26) RND(6)   x0 += k1;  x1 += ks2 + 1u;
    RND(17) RND(29) RND(16) RND(24)  x0 += ks2; x1 += k0 + 2u;
    RND(13) RND(15) RND(26) RND(6)   x0 += k0;  x1 += k1 + 3u;
    RND(17) RND(29) RND(16) RND(24)  x0 += k1;  x1 += ks2 + 4u;
    RND(13) RND(15) RND(26) RND(6)   x0 += ks2; x1 += k0 + 5u;
#undef RND
    const uint32_t bits = x0 ^ x1;
    float f = __uint_as_float((bits >> 9) | 0x3f800000u) - 1.0f;
    float u = fmaxf(f, 1.17549435e-38f);
    return -logf(-logf(u));
}

// ---------------- softmax+sample, finalize -----------------------------------
__global__ void sample_kernel() {
    const int b = blockIdx.x;
    const float* __restrict__ row = g_logits + (long)b * A_;
    const int tid = threadIdx.x;
    __shared__ float sred[256];
    __shared__ int   sidx[256];

    float mx = -3.402823466e38f;
    for (int a = tid; a < A_; a += 256) mx = fmaxf(mx, row[a]);
    sred[tid] = mx; __syncthreads();
    for (int s = 128; s; s >>= 1) {
        if (tid < s) sred[tid] = fmaxf(sred[tid], sred[tid + s]);
        __syncthreads();
    }
    const float rmax = sred[0]; __syncthreads();

    float sum = 0.f;
    for (int a = tid; a < A_; a += 256) sum += expf(row[a] - rmax);
    sred[tid] = sum; __syncthreads();
    for (int s = 128; s; s >>= 1) {
        if (tid < s) sred[tid] += sred[tid + s];
        __syncthreads();
    }
    const float rsum = sred[0]; __syncthreads();

    float bestv = -3.402823466e38f;
    int   besti = A_;
    for (int a = tid; a < A_; a += 256) {
        float p = expf(row[a] - rmax) / rsum;
        float v = p + gumbel_at((uint32_t)(b * A_ + a));
        if (v > bestv) { bestv = v; besti = a; }
    }
    sred[tid] = bestv; sidx[tid] = besti; __syncthreads();
    for (int s = 128; s; s >>= 1) {
        if (tid < s) {
            float v2 = sred[tid + s]; int i2 = sidx[tid + s];
            if (v2 > sred[tid] || (v2 == sred[tid] && i2 < sidx[tid])) {
                sred[tid] = v2; sidx[tid] = i2;
            }
        }
        __syncthreads();
    }
    if (tid == 0) {
        const int a = sidx[0];
        g_action[b] = a;
        float p = expf(row[a] - rmax) / rsum;
        p = fminf(fmaxf(p, 1e-7f), 1.0f - 1e-7f);
        g_rowloss[b] = -logf(p);
    }
}

__global__ void finalize_kernel(float* __restrict__ out, int out_size) {
    const int tid = threadIdx.x;
    __shared__ float red[256];
    red[tid] = g_rowloss[tid];
    __syncthreads();
    for (int s = 128; s; s >>= 1) {
        if (tid < s) red[tid] += red[tid + s];
        __syncthreads();
    }
    const float loss = red[0] / (float)B_;

    if (out_size == 1) {
        if (tid == 0) out[0] = loss;
        return;
    }
    if (tid < B_ && tid < out_size) out[tid] = (float)g_action[tid];
    if (tid == 0 && out_size > B_) out[B_] = loss;
    for (int i = B_ + 1 + tid; i < out_size; i += 256) out[i] = 0.0f;
}

// ---------------- launch -----------------------------------------------------
extern "C" void kernel_launch(void* const* d_in, const int* in_sizes, int n_in,
                              void* d_out, int out_size) {
    const float* inputs = (const float*)d_in[0];
    const float* Wx     = (const float*)d_in[1];
    const float* Wh     = (const float*)d_in[2];
    const float* b_rnn  = (const float*)d_in[3];
    const float* W1     = (const float*)d_in[4];
    const float* b1     = (const float*)d_in[5];
    const float* W2     = (const float*)d_in[6];
    const float* b2     = (const float*)d_in[7];

    float *xw, *h, *hid, *logits;
    cudaGetSymbolAddress((void**)&xw,     g_xw);
    cudaGetSymbolAddress((void**)&h,      g_hbuf);
    cudaGetSymbolAddress((void**)&hid,    g_hid);
    cudaGetSymbolAddress((void**)&logits, g_logits);

    // xw = inputs @ Wx + b_rnn   (M=65536, N=1024, K=512)
    sgemm_kernel<128, 128, 16, 8, 8, 256, false>
        <<<dim3(H_ / 128, (B_ * T_) / 128), 256>>>(
            B_ * T_, H_, F_, inputs, F_, Wx, H_, b_rnn, xw, H_);

    // persistent recurrence + fused dense1
    const int smem = (int)sizeof(RecurSmem);  // 65536 + 145408 = 210944
    cudaFuncSetAttribute(rnn_recur, cudaFuncAttributeMaxDynamicSharedMemorySize, smem);
    rnn_recur<<<NBLK, RTHREADS, smem>>>(xw, Wh, W1, b1, h, hid);

    // logits = hid @ W2 + b2   (N=1000, ragged)
    sgemm_kernel<32, 64, 16, 4, 4, 128, false>
        <<<dim3((A_ + 63) / 64, B_ / 32), 128>>>(
            B_, A_, H_, hid, H_, W2, A_, b2, logits, A_);

    sample_kernel<<<B_, 256>>>();
    finalize_kernel<<<1, 256>>>((float*)d_out, out_size);
}

// round 12
// speedup vs baseline: 1.1936x; 1.1936x over previous
#include <cuda_runtime.h>
#include <cuda_bf16.h>
#include <cstdint>

#define B_ 256
#define T_ 256
#define F_ 512
#define H_ 1024
#define A_ 1000

// recurrence: 128 blocks = 2 row-groups(128) x 8 col-groups(128) x 8 k-splits(128)
#define NBLK 128
#define RTHREADS 512
#define RROWS 128
#define RCOLS 128
#define RK    128
#define NSPLIT 8
#define BKr   64
#define SPAD  130   // staging pitch in u64 per k-row (128 + 2 pad)

// ---------------- scratch (static device globals; no allocation) -------------
__device__ float g_xw[(size_t)B_ * T_ * H_];     // input projection [B][T][H]
__device__ float g_hbuf[B_ * H_];                // hidden state
__device__ float g_part[NSPLIT][B_ * H_];        // k-split partials [q][m][n]
__device__ float g_hid[B_ * H_];
__device__ float g_logits[B_ * A_];
__device__ int   g_action[B_];
__device__ float g_rowloss[B_];

// grid barrier state (self-cleaning; safe across graph replays)
__device__ unsigned g_cnt = 0;
__device__ volatile unsigned g_gen = 0;

// ---------------- packed fp32x2 FMA helpers ----------------------------------
__device__ __forceinline__ unsigned long long pack2(float lo, float hi) {
    unsigned long long r;
    asm("mov.b64 %0, {%1, %2};" : "=l"(r) : "f"(lo), "f"(hi));
    return r;
}
__device__ __forceinline__ void unpack2(unsigned long long v, float& lo, float& hi) {
    asm("mov.b64 {%0, %1}, %2;" : "=f"(lo), "=f"(hi) : "l"(v));
}
__device__ __forceinline__ void ffma2(unsigned long long& d, unsigned long long a,
                                      unsigned long long b) {
    asm("fma.rn.f32x2 %0, %1, %2, %0;" : "+l"(d) : "l"(a), "l"(b));
}

// ---------------- tf32 split + mma.sync helpers ------------------------------
__device__ __forceinline__ void tf32_split(float x, uint32_t& u0, uint32_t& u1) {
    asm("cvt.rna.tf32.f32 %0, %1;" : "=r"(u0) : "f"(x));
    float r = x - __uint_as_float(u0);
    asm("cvt.rna.tf32.f32 %0, %1;" : "=r"(u1) : "f"(r));
}
__device__ __forceinline__ void mma_tf32(float c[4], const uint32_t a[4],
                                         const uint32_t b[2]) {
    asm volatile(
        "mma.sync.aligned.m16n8k8.row.col.f32.tf32.tf32.f32 "
        "{%0,%1,%2,%3}, {%4,%5,%6,%7}, {%8,%9}, {%0,%1,%2,%3};"
        : "+f"(c[0]), "+f"(c[1]), "+f"(c[2]), "+f"(c[3])
        : "r"(a[0]), "r"(a[1]), "r"(a[2]), "r"(a[3]), "r"(b[0]), "r"(b[1]));
}

// ---------------- phase-A 3xTF32 tensor GEMM ---------------------------------
// xw[65536,1024] = inputs[65536,512] @ Wx[512,1024] + b_rnn
// CTA tile 128x128, 8 warps (2x4), warp tile 64x32, K-chunks of 16, dbl-buffered.
// smem per term/operand: [16][PITA] fp32, PITA=136 (fragment loads conflict-free).
#define PITA 136
#define GA_CH 16
#define GA_NCH (F_ / GA_CH)        // 32 chunks
#define GA_TILE (GA_CH * PITA)     // floats per tile buffer

__global__ void __launch_bounds__(256, 1)
gemm_a_mma(const float* __restrict__ Ag, const float* __restrict__ Bg,
           const float* __restrict__ bias, float* __restrict__ C)
{
    extern __shared__ __align__(16) float sm[];
    float* sA0 = sm;                       // [2][16][PITA]
    float* sA1 = sm + 2 * GA_TILE;
    float* sB0 = sm + 4 * GA_TILE;
    float* sB1 = sm + 6 * GA_TILE;

    const int tid  = threadIdx.x;
    const int lane = tid & 31;
    const int w    = tid >> 5;
    const int wm   = w >> 2;               // 0..1 -> m offset wm*64
    const int wn   = w & 3;                // 0..3 -> n offset wn*32
    const int bm   = blockIdx.y * 128;
    const int bn   = blockIdx.x * 128;
    const int g    = lane >> 2;            // groupID
    const int tg   = lane & 3;             // threadID_in_group

    // staging indices
    const int a_k4  = tid >> 7;            // j adds 2
    const int a_row = tid & 127;
    const int b_k   = tid >> 5;            // j adds 8
    const int b_n4  = lane;

    float4 aReg[2], bReg[2];
    auto loadG = [&](int k0) {
#pragma unroll
        for (int j = 0; j < 2; ++j) {
            aReg[j] = __ldg((const float4*)(Ag + (size_t)(bm + a_row) * F_ +
                                            k0 + (a_k4 + 2 * j) * 4));
            bReg[j] = __ldg((const float4*)(Bg + (size_t)(k0 + b_k + 8 * j) * H_ +
                                            bn + b_n4 * 4));
        }
    };
    auto storeS = [&](int buf) {
        float* dA0 = sA0 + buf * GA_TILE;
        float* dA1 = sA1 + buf * GA_TILE;
        float* dB0 = sB0 + buf * GA_TILE;
        float* dB1 = sB1 + buf * GA_TILE;
#pragma unroll
        for (int j = 0; j < 2; ++j) {
            const int kb = (a_k4 + 2 * j) * 4;
            const float av[4] = {aReg[j].x, aReg[j].y, aReg[j].z, aReg[j].w};
#pragma unroll
            for (int e = 0; e < 4; ++e) {
                uint32_t u0, u1;
                tf32_split(av[e], u0, u1);
                dA0[(kb + e) * PITA + a_row] = __uint_as_float(u0);
                dA1[(kb + e) * PITA + a_row] = __uint_as_float(u1);
            }
            const int kr = b_k + 8 * j;
            const float bv[4] = {bReg[j].x, bReg[j].y, bReg[j].z, bReg[j].w};
            uint4 q0, q1;
            uint32_t* p0 = (uint32_t*)&q0;
            uint32_t* p1 = (uint32_t*)&q1;
#pragma unroll
            for (int e = 0; e < 4; ++e) tf32_split(bv[e], p0[e], p1[e]);
            *(uint4*)(dB0 + kr * PITA + b_n4 * 4) = q0;
            *(uint4*)(dB1 + kr * PITA + b_n4 * 4) = q1;
        }
    };

    float c[4][4][4];
#pragma unroll
    for (int i = 0; i < 4; ++i)
#pragma unroll
        for (int j = 0; j < 4; ++j)
#pragma unroll
            for (int e = 0; e < 4; ++e) c[i][j][e] = 0.0f;

    loadG(0);
    storeS(0);
    __syncthreads();

    for (int kt = 0; kt < GA_NCH; ++kt) {
        const int cur = kt & 1;
        if (kt + 1 < GA_NCH) loadG((kt + 1) * GA_CH);

        const float* cA0 = sA0 + cur * GA_TILE;
        const float* cA1 = sA1 + cur * GA_TILE;
        const float* cB0 = sB0 + cur * GA_TILE;
        const float* cB1 = sB1 + cur * GA_TILE;

#pragma unroll
        for (int s = 0; s < 2; ++s) {
            const int ko = s * 8;
            uint32_t bt0[4][2], bt1[4][2];
#pragma unroll
            for (int in = 0; in < 4; ++in) {
                const int an = wn * 32 + in * 8 + g;
                bt0[in][0] = __float_as_uint(cB0[(ko + tg) * PITA + an]);
                bt0[in][1] = __float_as_uint(cB0[(ko + tg + 4) * PITA + an]);
                bt1[in][0] = __float_as_uint(cB1[(ko + tg) * PITA + an]);
                bt1[in][1] = __float_as_uint(cB1[(ko + tg + 4) * PITA + an]);
            }
#pragma unroll
            for (int im = 0; im < 4; ++im) {
                const int am = wm * 64 + im * 16 + g;
                uint32_t a0[4], a1[4];
                a0[0] = __float_as_uint(cA0[(ko + tg) * PITA + am]);
                a0[1] = __float_as_uint(cA0[(ko + tg) * PITA + am + 8]);
                a0[2] = __float_as_uint(cA0[(ko + tg + 4) * PITA + am]);
                a0[3] = __float_as_uint(cA0[(ko + tg + 4) * PITA + am + 8]);
                a1[0] = __float_as_uint(cA1[(ko + tg) * PITA + am]);
                a1[1] = __float_as_uint(cA1[(ko + tg) * PITA + am + 8]);
                a1[2] = __float_as_uint(cA1[(ko + tg + 4) * PITA + am]);
                a1[3] = __float_as_uint(cA1[(ko + tg + 4) * PITA + am + 8]);
#pragma unroll
                for (int in = 0; in < 4; ++in) {
                    mma_tf32(c[im][in], a0, bt1[in]);   // small terms first
                    mma_tf32(c[im][in], a1, bt0[in]);
                    mma_tf32(c[im][in], a0, bt0[in]);
                }
            }
        }

        if (kt + 1 < GA_NCH) storeS(cur ^ 1);
        __syncthreads();
    }

    // epilogue: add bias, store fp32
#pragma unroll
    for (int im = 0; im < 4; ++im) {
        const int r0 = bm + wm * 64 + im * 16 + g;
#pragma unroll
        for (int in = 0; in < 4; ++in) {
            const int n0 = bn + wn * 32 + in * 8 + 2 * tg;
            float2 bv = *(const float2*)&bias[n0];
            float2 o0 = {c[im][in][0] + bv.x, c[im][in][1] + bv.y};
            float2 o1 = {c[im][in][2] + bv.x, c[im][in][3] + bv.y};
            *(float2*)&C[(size_t)r0 * H_ + n0]       = o0;
            *(float2*)&C[(size_t)(r0 + 8) * H_ + n0] = o1;
        }
    }
}

// ---------------- grid-wide barrier ------------------------------------------
__device__ __forceinline__ void grid_sync() {
    __syncthreads();
    if (threadIdx.x == 0) {
        __threadfence();
        unsigned gen = g_gen;
        unsigned old = atomicAdd(&g_cnt, 1u);
        if (old == NBLK - 1) {
            g_cnt = 0;
            __threadfence();
            g_gen = gen + 1;
        } else {
            while (g_gen == gen) { }
            __threadfence();
        }
    }
    __syncthreads();
}

// ---------------- persistent recurrence kernel (R8 config) -------------------
struct RecurSmem {
    float Whs[RK * RCOLS];                       // 64 KB slab
    unsigned long long hsd[2 * BKr * SPAD];      // 133 KB staging
};

__device__ __forceinline__ void stage_store(
    unsigned long long* __restrict__ hsd, int bufk0, int ko, int m_l,
    const float4 v[4])
{
#pragma unroll
    for (int j = 0; j < 4; ++j) {
        const int kl = bufk0 + ko + 16 * j;
        unsigned long long* d = &hsd[(size_t)kl * SPAD + m_l];
        d[0 * SPAD] = pack2(v[j].x, v[j].x);
        d[1 * SPAD] = pack2(v[j].y, v[j].y);
        d[2 * SPAD] = pack2(v[j].z, v[j].z);
        d[3 * SPAD] = pack2(v[j].w, v[j].w);
    }
}

__device__ __forceinline__ void compute_chunk(
    const unsigned long long* __restrict__ asb,
    const float* __restrict__ ws,
    unsigned long long acc[8][2])
{
#pragma unroll 16
    for (int kk = 0; kk < BKr; ++kk) {
        const unsigned long long* ar = asb + (size_t)kk * SPAD;
        ulonglong2 a01 = *(const ulonglong2*)(ar);
        ulonglong2 a23 = *(const ulonglong2*)(ar + 2);
        ulonglong2 a45 = *(const ulonglong2*)(ar + 4);
        ulonglong2 a67 = *(const ulonglong2*)(ar + 6);
        ulonglong2 b   = *(const ulonglong2*)(ws + (size_t)kk * RCOLS);
        ffma2(acc[0][0], a01.x, b.x); ffma2(acc[0][1], a01.x, b.y);
        ffma2(acc[1][0], a01.y, b.x); ffma2(acc[1][1], a01.y, b.y);
        ffma2(acc[2][0], a23.x, b.x); ffma2(acc[2][1], a23.x, b.y);
        ffma2(acc[3][0], a23.y, b.x); ffma2(acc[3][1], a23.y, b.y);
        ffma2(acc[4][0], a45.x, b.x); ffma2(acc[4][1], a45.x, b.y);
        ffma2(acc[5][0], a45.y, b.x); ffma2(acc[5][1], a45.y, b.y);
        ffma2(acc[6][0], a67.x, b.x); ffma2(acc[6][1], a67.x, b.y);
        ffma2(acc[7][0], a67.y, b.x); ffma2(acc[7][1], a67.y, b.y);
    }
}

__device__ __forceinline__ void tile_gemm_part(
    const float* __restrict__ hrow,
    const float* __restrict__ Whs,
    unsigned long long* __restrict__ hsd,
    int ty, int tx, int m_l, int ko,
    unsigned long long acc[8][2])
{
    float4 v[4];
#pragma unroll
    for (int j = 0; j < 4; ++j)
        v[j] = __ldcg((const float4*)(hrow + ko + 16 * j));
    stage_store(hsd, 0, ko, m_l, v);
    __syncthreads();

#pragma unroll
    for (int j = 0; j < 4; ++j)
        v[j] = __ldcg((const float4*)(hrow + BKr + ko + 16 * j));

    compute_chunk(&hsd[ty * 8], &Whs[tx * 4], acc);

    stage_store(hsd, BKr, ko, m_l, v);
    __syncthreads();

    compute_chunk(&hsd[(size_t)BKr * SPAD + ty * 8],
                  &Whs[(size_t)BKr * RCOLS + tx * 4], acc);
}

__device__ __forceinline__ void store_partials(
    unsigned long long acc[8][2], float* __restrict__ pq,
    int bm, int bn, int ty, int tx)
{
#pragma unroll
    for (int i = 0; i < 8; ++i) {
        const int m = bm + ty * 8 + i;
        float v0, v1, v2, v3;
        unpack2(acc[i][0], v0, v1);
        unpack2(acc[i][1], v2, v3);
        __stcg((float4*)&pq[(long)m * H_ + bn + tx * 4],
               make_float4(v0, v1, v2, v3));
    }
}

__global__ void __launch_bounds__(RTHREADS, 1)
rnn_recur(const float* __restrict__ xw, const float* __restrict__ Wh,
          const float* __restrict__ W1, const float* __restrict__ b1,
          float* __restrict__ h, float* __restrict__ hid)
{
    extern __shared__ __align__(16) char smraw[];
    RecurSmem* sm = (RecurSmem*)smraw;

    const int tid = threadIdx.x;
    const int bid = blockIdx.x;
    const int q = bid & 7;
    const int c = (bid >> 3) & 7;
    const int r = bid >> 6;
    const int bm = r * RROWS, bn = c * RCOLS, bk = q * RK;
    const int tx = tid & 31;
    const int ty = tid >> 5;
    const int m_l = tid >> 2;
    const int ko  = (tid & 3) * 4;
    const int gtid = bid * RTHREADS + tid;

    const int rm = gtid >> 8;
    const int rn4 = (gtid & 255) * 4;
    const long roff = (long)rm * H_ + rn4;

    for (int v = tid; v < RK * RCOLS / 4; v += RTHREADS) {
        int k = v >> 5, nq = v & 31;
        float4 wv = __ldg((const float4*)&Wh[(long)(bk + k) * H_ + bn + nq * 4]);
        *(float4*)&sm->Whs[k * RCOLS + nq * 4] = wv;
    }

    {
        float4 v = __ldg((const float4*)&xw[((long)rm * T_ + 0) * H_ + rn4]);
        v.x = fmaxf(v.x, 0.f); v.y = fmaxf(v.y, 0.f);
        v.z = fmaxf(v.z, 0.f); v.w = fmaxf(v.w, 0.f);
        __stcg((float4*)&h[roff], v);
    }
    grid_sync();

    for (int t = 1; t < T_; ++t) {
        float4 xv = __ldcg((const float4*)&xw[((long)rm * T_ + t) * H_ + rn4]);

        unsigned long long acc[8][2];
#pragma unroll
        for (int i = 0; i < 8; ++i) { acc[i][0] = 0ull; acc[i][1] = 0ull; }

        tile_gemm_part(&h[(long)(bm + m_l) * H_ + bk], sm->Whs, sm->hsd,
                       ty, tx, m_l, ko, acc);
        store_partials(acc, g_part[q], bm, bn, ty, tx);
        grid_sync();

        {
            float4 s = xv;
#pragma unroll
            for (int qq = 0; qq < NSPLIT; ++qq) {
                float4 p = __ldcg((const float4*)&g_part[qq][roff]);
                s.x += p.x; s.y += p.y; s.z += p.z; s.w += p.w;
            }
            s.x = fmaxf(s.x, 0.f); s.y = fmaxf(s.y, 0.f);
            s.z = fmaxf(s.z, 0.f); s.w = fmaxf(s.w, 0.f);
            __stcg((float4*)&h[roff], s);
        }
        grid_sync();
    }
    // h now holds h_last (h_256)

    // fused dense1: hid = relu(h_last @ W1 + b1) — swap slab to W1
    for (int v = tid; v < RK * RCOLS / 4; v += RTHREADS) {
        int k = v >> 5, nq = v & 31;
        float4 wv = __ldg((const float4*)&W1[(long)(bk + k) * H_ + bn + nq * 4]);
        *(float4*)&sm->Whs[k * RCOLS + nq * 4] = wv;
    }
    __syncthreads();
    {
        unsigned long long acc[8][2];
#pragma unroll
        for (int i = 0; i < 8; ++i) { acc[i][0] = 0ull; acc[i][1] = 0ull; }
        tile_gemm_part(&h[(long)(bm + m_l) * H_ + bk], sm->Whs, sm->hsd,
                       ty, tx, m_l, ko, acc);
        store_partials(acc, g_part[q], bm, bn, ty, tx);
        grid_sync();
        {
            float4 s = __ldg((const float4*)&b1[rn4]);
#pragma unroll
            for (int qq = 0; qq < NSPLIT; ++qq) {
                float4 p = __ldcg((const float4*)&g_part[qq][roff]);
                s.x += p.x; s.y += p.y; s.z += p.z; s.w += p.w;
            }
            s.x = fmaxf(s.x, 0.f); s.y = fmaxf(s.y, 0.f);
            s.z = fmaxf(s.z, 0.f); s.w = fmaxf(s.w, 0.f);
            __stcg((float4*)&hid[roff], s);
        }
    }
}

// ---------------- double-buffered SGEMM (dup-A; logits) ----------------------
template <int BM, int BN, int BK, int TM, int TN, int THREADS, bool RELU>
__global__ void __launch_bounds__(THREADS)
sgemm_kernel(int M, int N, int K,
             const float* __restrict__ A, int lda,
             const float* __restrict__ Bm, int ldb,
             const float* __restrict__ bias,
             float* __restrict__ C, int ldc)
{
    static_assert(TN % 4 == 0 && TM % 2 == 0, "");
    constexpr int TX = BN / TN;
    constexpr int TY = BM / TM;
    static_assert(TX * TY == THREADS, "");

    __shared__ __align__(16) unsigned long long As[2][BK][BM];
    __shared__ __align__(16) float Bs[2][BK][BN];

    const int tid = threadIdx.x;
    const int tx  = tid % TX;
    const int ty  = tid / TX;
    const int bm  = blockIdx.y * BM;
    const int bn  = blockIdx.x * BN;

    constexpr int A_VECS = BM * BK / 4;
    constexpr int A_PER  = A_VECS / THREADS;
    constexpr int B_VECS = BK * BN / 4;
    constexpr int B_PER  = B_VECS / THREADS;
    static_assert(A_VECS % THREADS == 0 && B_VECS % THREADS == 0, "");

    float4 aReg[A_PER];
    float4 bReg[B_PER];

    auto loadA = [&](int k0) {
#pragma unroll
        for (int i = 0; i < A_PER; ++i) {
            int v   = tid + i * THREADS;
            int row = v / (BK / 4);
            int kc  = (v % (BK / 4)) * 4;
            aReg[i] = *reinterpret_cast<const float4*>(
                &A[(long)(bm + row) * lda + k0 + kc]);
        }
    };
    auto loadB = [&](int k0) {
#pragma unroll
        for (int i = 0; i < B_PER; ++i) {
            int v    = tid + i * THREADS;
            int krow = v / (BN / 4);
            int nc   = (v % (BN / 4)) * 4;
            int col  = bn + nc;
            if (col < N)
                bReg[i] = *reinterpret_cast<const float4*>(
                    &Bm[(long)(k0 + krow) * ldb + col]);
            else
                bReg[i] = make_float4(0.f, 0.f, 0.f, 0.f);
        }
    };
    auto storeA = [&](int buf) {
#pragma unroll
        for (int i = 0; i < A_PER; ++i) {
            int v   = tid + i * THREADS;
            int row = v / (BK / 4);
            int kc  = (v % (BK / 4)) * 4;
            As[buf][kc + 0][row] = pack2(aReg[i].x, aReg[i].x);
            As[buf][kc + 1][row] = pack2(aReg[i].y, aReg[i].y);
            As[buf][kc + 2][row] = pack2(aReg[i].z, aReg[i].z);
            As[buf][kc + 3][row] = pack2(aReg[i].w, aReg[i].w);
        }
    };
    auto storeB = [&](int buf) {
#pragma unroll
        for (int i = 0; i < B_PER; ++i) {
            int v    = tid + i * THREADS;
            int krow = v / (BN / 4);
            int nc   = (v % (BN / 4)) * 4;
            *reinterpret_cast<float4*>(&Bs[buf][krow][nc]) = bReg[i];
        }
    };

    unsigned long long acc[TM][TN / 2];
#pragma unroll
    for (int i = 0; i < TM; ++i)
#pragma unroll
        for (int j = 0; j < TN / 2; ++j) acc[i][j] = 0ull;

    loadA(0); loadB(0);
    storeA(0); storeB(0);
    __syncthreads();

    const int nTiles = K / BK;
    for (int kt = 0; kt < nTiles; ++kt) {
        const int cur = kt & 1, nxt = cur ^ 1;
        if (kt + 1 < nTiles) { loadA((kt + 1) * BK); loadB((kt + 1) * BK); }

#pragma unroll
        for (int kk = 0; kk < BK; ++kk) {
            unsigned long long a2[TM];
#pragma unroll
            for (int i = 0; i < TM; i += 2) {
                ulonglong2 t = *reinterpret_cast<const ulonglong2*>(
                    &As[cur][kk][ty * TM + i]);
                a2[i] = t.x; a2[i + 1] = t.y;
            }
            unsigned long long b2[TN / 2];
#pragma unroll
            for (int j = 0; j < TN / 4; ++j) {
                ulonglong2 bv = *reinterpret_cast<const ulonglong2*>(
                    &Bs[cur][kk][tx * TN + 4 * j]);
                b2[2 * j] = bv.x; b2[2 * j + 1] = bv.y;
            }
#pragma unroll
            for (int i = 0; i < TM; ++i)
#pragma unroll
                for (int j = 0; j < TN / 2; ++j) ffma2(acc[i][j], a2[i], b2[j]);
        }

        if (kt + 1 < nTiles) { storeA(nxt); storeB(nxt); }
        __syncthreads();
    }

#pragma unroll
    for (int i = 0; i < TM; ++i) {
        const int m = bm + ty * TM + i;
#pragma unroll
        for (int j = 0; j < TN / 2; ++j) {
            float lo, hi;
            unpack2(acc[i][j], lo, hi);
            float v[2] = {lo, hi};
            const int n0 = bn + tx * TN + 2 * j;
#pragma unroll
            for (int e = 0; e < 2; ++e) {
                const int n = n0 + e;
                if (n < N) {
                    float cv = v[e];
                    if (bias) cv += bias[n];
                    if (RELU) cv = fmaxf(cv, 0.0f);
                    C[(long)m * ldc + n] = cv;
                }
            }
        }
    }
}

// ---------------- threefry2x32 / JAX gumbel ----------------------------------
__device__ __forceinline__ float gumbel_at(uint32_t idx) {
    const uint32_t k0 = 0u, k1 = 42u;
    const uint32_t ks2 = k0 ^ k1 ^ 0x1BD11BDAu;
    uint32_t x0 = k0;
    uint32_t x1 = idx + k1;
#define RND(r) { x0 += x1; x1 = ((x1 << (r)) | (x1 >> (32 - (r)))) ^ x0; }
    RND(13) RND(15) RND(26) RND(6)   x0 += k1;  x1 += ks2 + 1u;
    RND(17) RND(29) RND(16) RND(24)  x0 += ks2; x1 += k0 + 2u;
    RND(13) RND(15) RND(26) RND(6)   x0 += k0;  x1 += k1 + 3u;
    RND(17) RND(29) RND(16) RND(24)  x0 += k1;  x1 += ks2 + 4u;
    RND(13) RND(15) RND(26) RND(6)   x0 += ks2; x1 += k0 + 5u;
#undef RND
    const uint32_t bits = x0 ^ x1;
    float f = __uint_as_float((bits >> 9) | 0x3f800000u) - 1.0f;
    float u = fmaxf(f, 1.17549435e-38f);
    return -logf(-logf(u));
}

// ---------------- softmax+sample, finalize -----------------------------------
__global__ void sample_kernel() {
    const int b = blockIdx.x;
    const float* __restrict__ row = g_logits + (long)b * A_;
    const int tid = threadIdx.x;
    __shared__ float sred[256];
    __shared__ int   sidx[256];

    float mx = -3.402823466e38f;
    for (int a = tid; a < A_; a += 256) mx = fmaxf(mx, row[a]);
    sred[tid] = mx; __syncthreads();
    for (int s = 128; s; s >>= 1) {
        if (tid < s) sred[tid] = fmaxf(sred[tid], sred[tid + s]);
        __syncthreads();
    }
    const float rmax = sred[0]; __syncthreads();

    float sum = 0.f;
    for (int a = tid; a < A_; a += 256) sum += expf(row[a] - rmax);
    sred[tid] = sum; __syncthreads();
    for (int s = 128; s; s >>= 1) {
        if (tid < s) sred[tid] += sred[tid + s];
        __syncthreads();
    }
    const float rsum = sred[0]; __syncthreads();

    float bestv = -3.402823466e38f;
    int   besti = A_;
    for (int a = tid; a < A_; a += 256) {
        float p = expf(row[a] - rmax) / rsum;
        float v = p + gumbel_at((uint32_t)(b * A_ + a));
        if (v > bestv) { bestv = v; besti = a; }
    }
    sred[tid] = bestv; sidx[tid] = besti; __syncthreads();
    for (int s = 128; s; s >>= 1) {
        if (tid < s) {
            float v2 = sred[tid + s]; int i2 = sidx[tid + s];
            if (v2 > sred[tid] || (v2 == sred[tid] && i2 < sidx[tid])) {
                sred[tid] = v2; sidx[tid] = i2;
            }
        }
        __syncthreads();
    }
    if (tid == 0) {
        const int a = sidx[0];
        g_action[b] = a;
        float p = expf(row[a] - rmax) / rsum;
        p = fminf(fmaxf(p, 1e-7f), 1.0f - 1e-7f);
        g_rowloss[b] = -logf(p);
    }
}

__global__ void finalize_kernel(float* __restrict__ out, int out_size) {
    const int tid = threadIdx.x;
    __shared__ float red[256];
    red[tid] = g_rowloss[tid];
    __syncthreads();
    for (int s = 128; s; s >>= 1) {
        if (tid < s) red[tid] += red[tid + s];
        __syncthreads();
    }
    const float loss = red[0] / (float)B_;

    if (out_size == 1) {
        if (tid == 0) out[0] = loss;
        return;
    }
    if (tid < B_ && tid < out_size) out[tid] = (float)g_action[tid];
    if (tid == 0 && out_size > B_) out[B_] = loss;
    for (int i = B_ + 1 + tid; i < out_size; i += 256) out[i] = 0.0f;
}

// ---------------- launch -----------------------------------------------------
extern "C" void kernel_launch(void* const* d_in, const int* in_sizes, int n_in,
                              void* d_out, int out_size) {
    const float* inputs = (const float*)d_in[0];
    const float* Wx     = (const float*)d_in[1];
    const float* Wh     = (const float*)d_in[2];
    const float* b_rnn  = (const float*)d_in[3];
    const float* W1     = (const float*)d_in[4];
    const float* b1     = (const float*)d_in[5];
    const float* W2     = (const float*)d_in[6];
    const float* b2     = (const float*)d_in[7];

    float *xw, *h, *hid, *logits;
    cudaGetSymbolAddress((void**)&xw,     g_xw);
    cudaGetSymbolAddress((void**)&h,      g_hbuf);
    cudaGetSymbolAddress((void**)&hid,    g_hid);
    cudaGetSymbolAddress((void**)&logits, g_logits);

    // xw = inputs @ Wx + b_rnn  — 3xTF32 tensor-core GEMM
    const int ga_smem = 8 * GA_TILE * 4;   // 69632 B
    cudaFuncSetAttribute(gemm_a_mma,
                         cudaFuncAttributeMaxDynamicSharedMemorySize, ga_smem);
    gemm_a_mma<<<dim3(H_ / 128, (B_ * T_) / 128), 256, ga_smem>>>(
        inputs, Wx, b_rnn, xw);

    // persistent recurrence + fused dense1
    const int smem = (int)sizeof(RecurSmem);
    cudaFuncSetAttribute(rnn_recur, cudaFuncAttributeMaxDynamicSharedMemorySize, smem);
    rnn_recur<<<NBLK, RTHREADS, smem>>>(xw, Wh, W1, b1, h, hid);

    // logits = hid @ W2 + b2   (N=1000, ragged)
    sgemm_kernel<32, 64, 16, 4, 4, 128, false>
        <<<dim3((A_ + 63) / 64, B_ / 32), 128>>>(
            B_, A_, H_, hid, H_, W2, A_, b2, logits, A_);

    sample_kernel<<<B_, 256>>>();
    finalize_kernel<<<1, 256>>>((float*)d_out, out_size);
}

// round 13
// speedup vs baseline: 1.4327x; 1.2003x over previous
#include <cuda_runtime.h>
#include <cuda_bf16.h>
#include <cstdint>

#define B_ 256
#define T_ 256
#define F_ 512
#define H_ 1024
#define A_ 1000

// recurrence: 128 blocks = 2 row-groups(128) x 8 col-groups(128) x 8 k-splits(128)
#define NBLK 128
#define RTHREADS 512
#define RROWS 128
#define RCOLS 128
#define RK    128
#define NSPLIT 8
#define MPI   136   // smem pitch (floats): conflict-free mma fragment loads

// ---------------- scratch (static device globals; no allocation) -------------
__device__ float g_xw[(size_t)B_ * T_ * H_];     // input projection [B][T][H]
__device__ float g_hbuf[B_ * H_];                // hidden state
__device__ float g_part[NSPLIT][B_ * H_];        // k-split partials [q][m][n]
__device__ float g_hid[B_ * H_];
__device__ float g_logits[B_ * A_];
__device__ int   g_action[B_];
__device__ float g_rowloss[B_];

// grid barrier state (self-cleaning; safe across graph replays)
__device__ unsigned g_cnt = 0;
__device__ volatile unsigned g_gen = 0;

// ---------------- packed fp32x2 FMA helpers (sgemm for logits) ---------------
__device__ __forceinline__ unsigned long long pack2(float lo, float hi) {
    unsigned long long r;
    asm("mov.b64 %0, {%1, %2};" : "=l"(r) : "f"(lo), "f"(hi));
    return r;
}
__device__ __forceinline__ void unpack2(unsigned long long v, float& lo, float& hi) {
    asm("mov.b64 {%0, %1}, %2;" : "=f"(lo), "=f"(hi) : "l"(v));
}
__device__ __forceinline__ void ffma2(unsigned long long& d, unsigned long long a,
                                      unsigned long long b) {
    asm("fma.rn.f32x2 %0, %1, %2, %0;" : "+l"(d) : "l"(a), "l"(b));
}

// ---------------- tf32 split + mma.sync helpers ------------------------------
__device__ __forceinline__ void tf32_split(float x, uint32_t& u0, uint32_t& u1) {
    asm("cvt.rna.tf32.f32 %0, %1;" : "=r"(u0) : "f"(x));
    float r = x - __uint_as_float(u0);
    asm("cvt.rna.tf32.f32 %0, %1;" : "=r"(u1) : "f"(r));
}
__device__ __forceinline__ void mma_tf32(float c[4], const uint32_t a[4],
                                         const uint32_t b[2]) {
    asm volatile(
        "mma.sync.aligned.m16n8k8.row.col.f32.tf32.tf32.f32 "
        "{%0,%1,%2,%3}, {%4,%5,%6,%7}, {%8,%9}, {%0,%1,%2,%3};"
        : "+f"(c[0]), "+f"(c[1]), "+f"(c[2]), "+f"(c[3])
        : "r"(a[0]), "r"(a[1]), "r"(a[2]), "r"(a[3]), "r"(b[0]), "r"(b[1]));
}

// ---------------- phase-A 3xTF32 tensor GEMM (unchanged from R12) ------------
#define PITA 136
#define GA_CH 16
#define GA_NCH (F_ / GA_CH)        // 32 chunks
#define GA_TILE (GA_CH * PITA)

__global__ void __launch_bounds__(256, 1)
gemm_a_mma(const float* __restrict__ Ag, const float* __restrict__ Bg,
           const float* __restrict__ bias, float* __restrict__ C)
{
    extern __shared__ __align__(16) float sm[];
    float* sA0 = sm;
    float* sA1 = sm + 2 * GA_TILE;
    float* sB0 = sm + 4 * GA_TILE;
    float* sB1 = sm + 6 * GA_TILE;

    const int tid  = threadIdx.x;
    const int lane = tid & 31;
    const int w    = tid >> 5;
    const int wm   = w >> 2;
    const int wn   = w & 3;
    const int bm   = blockIdx.y * 128;
    const int bn   = blockIdx.x * 128;
    const int g    = lane >> 2;
    const int tg   = lane & 3;

    const int a_k4  = tid >> 7;
    const int a_row = tid & 127;
    const int b_k   = tid >> 5;
    const int b_n4  = lane;

    float4 aReg[2], bReg[2];
    auto loadG = [&](int k0) {
#pragma unroll
        for (int j = 0; j < 2; ++j) {
            aReg[j] = __ldg((const float4*)(Ag + (size_t)(bm + a_row) * F_ +
                                            k0 + (a_k4 + 2 * j) * 4));
            bReg[j] = __ldg((const float4*)(Bg + (size_t)(k0 + b_k + 8 * j) * H_ +
                                            bn + b_n4 * 4));
        }
    };
    auto storeS = [&](int buf) {
        float* dA0 = sA0 + buf * GA_TILE;
        float* dA1 = sA1 + buf * GA_TILE;
        float* dB0 = sB0 + buf * GA_TILE;
        float* dB1 = sB1 + buf * GA_TILE;
#pragma unroll
        for (int j = 0; j < 2; ++j) {
            const int kb = (a_k4 + 2 * j) * 4;
            const float av[4] = {aReg[j].x, aReg[j].y, aReg[j].z, aReg[j].w};
#pragma unroll
            for (int e = 0; e < 4; ++e) {
                uint32_t u0, u1;
                tf32_split(av[e], u0, u1);
                dA0[(kb + e) * PITA + a_row] = __uint_as_float(u0);
                dA1[(kb + e) * PITA + a_row] = __uint_as_float(u1);
            }
            const int kr = b_k + 8 * j;
            const float bv[4] = {bReg[j].x, bReg[j].y, bReg[j].z, bReg[j].w};
            uint4 q0, q1;
            uint32_t* p0 = (uint32_t*)&q0;
            uint32_t* p1 = (uint32_t*)&q1;
#pragma unroll
            for (int e = 0; e < 4; ++e) tf32_split(bv[e], p0[e], p1[e]);
            *(uint4*)(dB0 + kr * PITA + b_n4 * 4) = q0;
            *(uint4*)(dB1 + kr * PITA + b_n4 * 4) = q1;
        }
    };

    float c[4][4][4];
#pragma unroll
    for (int i = 0; i < 4; ++i)
#pragma unroll
        for (int j = 0; j < 4; ++j)
#pragma unroll
            for (int e = 0; e < 4; ++e) c[i][j][e] = 0.0f;

    loadG(0);
    storeS(0);
    __syncthreads();

    for (int kt = 0; kt < GA_NCH; ++kt) {
        const int cur = kt & 1;
        if (kt + 1 < GA_NCH) loadG((kt + 1) * GA_CH);

        const float* cA0 = sA0 + cur * GA_TILE;
        const float* cA1 = sA1 + cur * GA_TILE;
        const float* cB0 = sB0 + cur * GA_TILE;
        const float* cB1 = sB1 + cur * GA_TILE;

#pragma unroll
        for (int s = 0; s < 2; ++s) {
            const int ko = s * 8;
            uint32_t bt0[4][2], bt1[4][2];
#pragma unroll
            for (int in = 0; in < 4; ++in) {
                const int an = wn * 32 + in * 8 + g;
                bt0[in][0] = __float_as_uint(cB0[(ko + tg) * PITA + an]);
                bt0[in][1] = __float_as_uint(cB0[(ko + tg + 4) * PITA + an]);
                bt1[in][0] = __float_as_uint(cB1[(ko + tg) * PITA + an]);
                bt1[in][1] = __float_as_uint(cB1[(ko + tg + 4) * PITA + an]);
            }
#pragma unroll
            for (int im = 0; im < 4; ++im) {
                const int am = wm * 64 + im * 16 + g;
                uint32_t a0[4], a1[4];
                a0[0] = __float_as_uint(cA0[(ko + tg) * PITA + am]);
                a0[1] = __float_as_uint(cA0[(ko + tg) * PITA + am + 8]);
                a0[2] = __float_as_uint(cA0[(ko + tg + 4) * PITA + am]);
                a0[3] = __float_as_uint(cA0[(ko + tg + 4) * PITA + am + 8]);
                a1[0] = __float_as_uint(cA1[(ko + tg) * PITA + am]);
                a1[1] = __float_as_uint(cA1[(ko + tg) * PITA + am + 8]);
                a1[2] = __float_as_uint(cA1[(ko + tg + 4) * PITA + am]);
                a1[3] = __float_as_uint(cA1[(ko + tg + 4) * PITA + am + 8]);
#pragma unroll
                for (int in = 0; in < 4; ++in) {
                    mma_tf32(c[im][in], a0, bt1[in]);
                    mma_tf32(c[im][in], a1, bt0[in]);
                    mma_tf32(c[im][in], a0, bt0[in]);
                }
            }
        }

        if (kt + 1 < GA_NCH) storeS(cur ^ 1);
        __syncthreads();
    }

#pragma unroll
    for (int im = 0; im < 4; ++im) {
        const int r0 = bm + wm * 64 + im * 16 + g;
#pragma unroll
        for (int in = 0; in < 4; ++in) {
            const int n0 = bn + wn * 32 + in * 8 + 2 * tg;
            float2 bv = *(const float2*)&bias[n0];
            float2 o0 = {c[im][in][0] + bv.x, c[im][in][1] + bv.y};
            float2 o1 = {c[im][in][2] + bv.x, c[im][in][3] + bv.y};
            *(float2*)&C[(size_t)r0 * H_ + n0]       = o0;
            *(float2*)&C[(size_t)(r0 + 8) * H_ + n0] = o1;
        }
    }
}

// ---------------- grid-wide barrier ------------------------------------------
__device__ __forceinline__ void grid_sync() {
    __syncthreads();
    if (threadIdx.x == 0) {
        __threadfence();
        unsigned gen = g_gen;
        unsigned old = atomicAdd(&g_cnt, 1u);
        if (old == NBLK - 1) {
            g_cnt = 0;
            __threadfence();
            g_gen = gen + 1;
        } else {
            while (g_gen == gen) { }
            __threadfence();
        }
    }
    __syncthreads();
}

// ---------------- persistent recurrence kernel: 3xTF32 mma -------------------
// Block (r,c,q): rows [r*128,+128), cols [c*128,+128), k in [q*128,+128).
// Wh slab pre-split ONCE into 2 tf32 terms, [k][n] pitch-136 (139 KB resident).
// h staged per step in 4 chunks of 32 k, double-buffered, split to 2 terms,
// stored [k][m] with column XOR-swizzle by (k>>3)&3 (conflict-free stores AND
// fragment loads). 16 warps in 4x4 grid; warp tile 32x32; 24 HMMA/k-step.

struct RecurSmem {
    float W0[RK * MPI];          // 69632 B
    float W1s[RK * MPI];         // 69632 B
    float A0[2 * 32 * MPI];      // 34816 B (2 staging buffers, term 0)
    float A1[2 * 32 * MPI];      // 34816 B (term 1)
};                               // total 208896 B

__device__ __forceinline__ void split_slab(
    const float* __restrict__ Wg, float* __restrict__ sW0,
    float* __restrict__ sW1, int bk, int bn, int tid)
{
    for (int v = tid; v < RK * RCOLS / 4; v += RTHREADS) {
        int k = v >> 5, n4 = (v & 31) * 4;
        float4 wv = __ldg((const float4*)&Wg[(long)(bk + k) * H_ + bn + n4]);
        const float we[4] = {wv.x, wv.y, wv.z, wv.w};
#pragma unroll
        for (int e = 0; e < 4; ++e) {
            uint32_t u0, u1;
            tf32_split(we[e], u0, u1);
            sW0[k * MPI + n4 + e] = __uint_as_float(u0);
            sW1[k * MPI + n4 + e] = __uint_as_float(u1);
        }
    }
}

__device__ __forceinline__ void stage_chunk(
    float* __restrict__ sA0, float* __restrict__ sA1, int buf,
    int kq, int mcol, const float4 va[2])
{
    float* d0 = sA0 + buf * (32 * MPI);
    float* d1 = sA1 + buf * (32 * MPI);
#pragma unroll
    for (int j = 0; j < 2; ++j) {
        const float v[4] = {va[j].x, va[j].y, va[j].z, va[j].w};
#pragma unroll
        for (int e = 0; e < 4; ++e) {
            uint32_t u0, u1;
            tf32_split(v[e], u0, u1);
            const int kl = kq + j * 4 + e;
            d0[kl * MPI + mcol] = __uint_as_float(u0);
            d1[kl * MPI + mcol] = __uint_as_float(u1);
        }
    }
}

// full 128x128x128 tile GEMM: h (global) x resident slab -> c fragments
__device__ __forceinline__ void mma_tile(
    const float* __restrict__ hrow,            // &h[(bm+m_s)*H_ + bk + kq]
    const float* __restrict__ sW0, const float* __restrict__ sW1,
    float* __restrict__ sA0, float* __restrict__ sA1,
    int wr, int wc, int g, int tg, int mcol, int kq,
    float c[2][4][4])
{
    float4 va[2];
    va[0] = __ldcg((const float4*)(hrow));
    va[1] = __ldcg((const float4*)(hrow + 4));
    stage_chunk(sA0, sA1, 0, kq, mcol, va);
    __syncthreads();

    for (int ch = 0; ch < 4; ++ch) {
        const int buf = ch & 1;
        if (ch < 3) {
            va[0] = __ldcg((const float4*)(hrow + (ch + 1) * 32));
            va[1] = __ldcg((const float4*)(hrow + (ch + 1) * 32 + 4));
        }

        const float* cA0 = sA0 + buf * (32 * MPI);
        const float* cA1 = sA1 + buf * (32 * MPI);
#pragma unroll
        for (int ks = 0; ks < 4; ++ks) {
            const int kb = ch * 32 + ks * 8;   // slab (B) k
            const int ka = ks * 8;             // staging (A) k
            const int msw = ks << 3;
            uint32_t bt0[4][2], bt1[4][2];
#pragma unroll
            for (int in = 0; in < 4; ++in) {
                const int an = wc * 32 + in * 8 + g;
                bt0[in][0] = __float_as_uint(sW0[(kb + tg) * MPI + an]);
                bt0[in][1] = __float_as_uint(sW0[(kb + tg + 4) * MPI + an]);
                bt1[in][0] = __float_as_uint(sW1[(kb + tg) * MPI + an]);
                bt1[in][1] = __float_as_uint(sW1[(kb + tg + 4) * MPI + an]);
            }
#pragma unroll
            for (int im = 0; im < 2; ++im) {
                const int am  = (wr * 32 + im * 16 + g) ^ msw;
                const int am8 = (wr * 32 + im * 16 + g + 8) ^ msw;
                uint32_t a0[4], a1[4];
                a0[0] = __float_as_uint(cA0[(ka + tg) * MPI + am]);
                a0[1] = __float_as_uint(cA0[(ka + tg) * MPI + am8]);
                a0[2] = __float_as_uint(cA0[(ka + tg + 4) * MPI + am]);
                a0[3] = __float_as_uint(cA0[(ka + tg + 4) * MPI + am8]);
                a1[0] = __float_as_uint(cA1[(ka + tg) * MPI + am]);
                a1[1] = __float_as_uint(cA1[(ka + tg) * MPI + am8]);
                a1[2] = __float_as_uint(cA1[(ka + tg + 4) * MPI + am]);
                a1[3] = __float_as_uint(cA1[(ka + tg + 4) * MPI + am8]);
#pragma unroll
                for (int in = 0; in < 4; ++in) {
                    mma_tf32(c[im][in], a0, bt1[in]);
                    mma_tf32(c[im][in], a1, bt0[in]);
                    mma_tf32(c[im][in], a0, bt0[in]);
                }
            }
        }

        if (ch < 3) stage_chunk(sA0, sA1, buf ^ 1, kq, mcol, va);
        __syncthreads();
    }
}

__device__ __forceinline__ void store_partials(
    float c[2][4][4], float* __restrict__ pq,
    int bm, int bn, int wr, int wc, int g, int tg)
{
#pragma unroll
    for (int im = 0; im < 2; ++im) {
        const int r0 = bm + wr * 32 + im * 16 + g;
#pragma unroll
        for (int in = 0; in < 4; ++in) {
            const int n0 = bn + wc * 32 + in * 8 + 2 * tg;
            __stcg((float2*)&pq[(long)r0 * H_ + n0],
                   make_float2(c[im][in][0], c[im][in][1]));
            __stcg((float2*)&pq[(long)(r0 + 8) * H_ + n0],
                   make_float2(c[im][in][2], c[im][in][3]));
        }
    }
}

__global__ void __launch_bounds__(RTHREADS, 1)
rnn_recur(const float* __restrict__ xw, const float* __restrict__ Wh,
          const float* __restrict__ W1, const float* __restrict__ b1,
          float* __restrict__ h, float* __restrict__ hid)
{
    extern __shared__ __align__(16) char smraw[];
    RecurSmem* sm = (RecurSmem*)smraw;

    const int tid = threadIdx.x;
    const int bid = blockIdx.x;
    const int q = bid & 7;
    const int c_ = (bid >> 3) & 7;
    const int r = bid >> 6;
    const int bm = r * RROWS, bn = c_ * RCOLS, bk = q * RK;

    const int w  = tid >> 5;
    const int wr = w >> 2, wc = w & 3;
    const int lane = tid & 31;
    const int g  = lane >> 2;
    const int tg = lane & 3;

    // staging mapping
    const int m_s = tid >> 2;          // 0..127
    const int kq  = (tid & 3) * 8;     // {0,8,16,24}
    const int mcol = m_s ^ ((tid & 3) << 3);   // XOR swizzle, (tid&3) == kl>>3

    const int gtid = bid * RTHREADS + tid;
    const int rm = gtid >> 8;
    const int rn4 = (gtid & 255) * 4;
    const long roff = (long)rm * H_ + rn4;

    // pre-split Wh slab (resident for all 255 steps)
    split_slab(Wh, sm->W0, sm->W1s, bk, bn, tid);

    // h_1 = relu(xw[:,0,:])
    {
        float4 v = __ldg((const float4*)&xw[((long)rm * T_ + 0) * H_ + rn4]);
        v.x = fmaxf(v.x, 0.f); v.y = fmaxf(v.y, 0.f);
        v.z = fmaxf(v.z, 0.f); v.w = fmaxf(v.w, 0.f);
        __stcg((float4*)&h[roff], v);
    }
    grid_sync();

    for (int t = 1; t < T_; ++t) {
        float4 xv = __ldcg((const float4*)&xw[((long)rm * T_ + t) * H_ + rn4]);

        float cf[2][4][4];
#pragma unroll
        for (int i = 0; i < 2; ++i)
#pragma unroll
            for (int j = 0; j < 4; ++j)
#pragma unroll
                for (int e = 0; e < 4; ++e) cf[i][j][e] = 0.0f;

        mma_tile(&h[(long)(bm + m_s) * H_ + bk + kq], sm->W0, sm->W1s,
                 sm->A0, sm->A1, wr, wc, g, tg, mcol, kq, cf);
        store_partials(cf, g_part[q], bm, bn, wr, wc, g, tg);
        grid_sync();

        // reduce: h = relu(xw[:,t,:] + sum_q partial_q)
        {
            float4 s = xv;
#pragma unroll
            for (int qq = 0; qq < NSPLIT; ++qq) {
                float4 p = __ldcg((const float4*)&g_part[qq][roff]);
                s.x += p.x; s.y += p.y; s.z += p.z; s.w += p.w;
            }
            s.x = fmaxf(s.x, 0.f); s.y = fmaxf(s.y, 0.f);
            s.z = fmaxf(s.z, 0.f); s.w = fmaxf(s.w, 0.f);
            __stcg((float4*)&h[roff], s);
        }
        grid_sync();
    }
    // h now holds h_last (h_256)

    // fused dense1: hid = relu(h_last @ W1 + b1) — re-split slab from W1
    split_slab(W1, sm->W0, sm->W1s, bk, bn, tid);
    __syncthreads();
    {
        float cf[2][4][4];
#pragma unroll
        for (int i = 0; i < 2; ++i)
#pragma unroll
            for (int j = 0; j < 4; ++j)
#pragma unroll
                for (int e = 0; e < 4; ++e) cf[i][j][e] = 0.0f;
        mma_tile(&h[(long)(bm + m_s) * H_ + bk + kq], sm->W0, sm->W1s,
                 sm->A0, sm->A1, wr, wc, g, tg, mcol, kq, cf);
        store_partials(cf, g_part[q], bm, bn, wr, wc, g, tg);
        grid_sync();
        {
            float4 s = __ldg((const float4*)&b1[rn4]);
#pragma unroll
            for (int qq = 0; qq < NSPLIT; ++qq) {
                float4 p = __ldcg((const float4*)&g_part[qq][roff]);
                s.x += p.x; s.y += p.y; s.z += p.z; s.w += p.w;
            }
            s.x = fmaxf(s.x, 0.f); s.y = fmaxf(s.y, 0.f);
            s.z = fmaxf(s.z, 0.f); s.w = fmaxf(s.w, 0.f);
            __stcg((float4*)&hid[roff], s);
        }
    }
}

// ---------------- double-buffered SGEMM (dup-A; logits) ----------------------
template <int BM, int BN, int BK, int TM, int TN, int THREADS, bool RELU>
__global__ void __launch_bounds__(THREADS)
sgemm_kernel(int M, int N, int K,
             const float* __restrict__ A, int lda,
             const float* __restrict__ Bm, int ldb,
             const float* __restrict__ bias,
             float* __restrict__ C, int ldc)
{
    static_assert(TN % 4 == 0 && TM % 2 == 0, "");
    constexpr int TX = BN / TN;
    constexpr int TY = BM / TM;
    static_assert(TX * TY == THREADS, "");

    __shared__ __align__(16) unsigned long long As[2][BK][BM];
    __shared__ __align__(16) float Bs[2][BK][BN];

    const int tid = threadIdx.x;
    const int tx  = tid % TX;
    const int ty  = tid / TX;
    const int bm  = blockIdx.y * BM;
    const int bn  = blockIdx.x * BN;

    constexpr int A_VECS = BM * BK / 4;
    constexpr int A_PER  = A_VECS / THREADS;
    constexpr int B_VECS = BK * BN / 4;
    constexpr int B_PER  = B_VECS / THREADS;
    static_assert(A_VECS % THREADS == 0 && B_VECS % THREADS == 0, "");

    float4 aReg[A_PER];
    float4 bReg[B_PER];

    auto loadA = [&](int k0) {
#pragma unroll
        for (int i = 0; i < A_PER; ++i) {
            int v   = tid + i * THREADS;
            int row = v / (BK / 4);
            int kc  = (v % (BK / 4)) * 4;
            aReg[i] = *reinterpret_cast<const float4*>(
                &A[(long)(bm + row) * lda + k0 + kc]);
        }
    };
    auto loadB = [&](int k0) {
#pragma unroll
        for (int i = 0; i < B_PER; ++i) {
            int v    = tid + i * THREADS;
            int krow = v / (BN / 4);
            int nc   = (v % (BN / 4)) * 4;
            int col  = bn + nc;
            if (col < N)
                bReg[i] = *reinterpret_cast<const float4*>(
                    &Bm[(long)(k0 + krow) * ldb + col]);
            else
                bReg[i] = make_float4(0.f, 0.f, 0.f, 0.f);
        }
    };
    auto storeA = [&](int buf) {
#pragma unroll
        for (int i = 0; i < A_PER; ++i) {
            int v   = tid + i * THREADS;
            int row = v / (BK / 4);
            int kc  = (v % (BK / 4)) * 4;
            As[buf][kc + 0][row] = pack2(aReg[i].x, aReg[i].x);
            As[buf][kc + 1][row] = pack2(aReg[i].y, aReg[i].y);
            As[buf][kc + 2][row] = pack2(aReg[i].z, aReg[i].z);
            As[buf][kc + 3][row] = pack2(aReg[i].w, aReg[i].w);
        }
    };
    auto storeB = [&](int buf) {
#pragma unroll
        for (int i = 0; i < B_PER; ++i) {
            int v    = tid + i * THREADS;
            int krow = v / (BN / 4);
            int nc   = (v % (BN / 4)) * 4;
            *reinterpret_cast<float4*>(&Bs[buf][krow][nc]) = bReg[i];
        }
    };

    unsigned long long acc[TM][TN / 2];
#pragma unroll
    for (int i = 0; i < TM; ++i)
#pragma unroll
        for (int j = 0; j < TN / 2; ++j) acc[i][j] = 0ull;

    loadA(0); loadB(0);
    storeA(0); storeB(0);
    __syncthreads();

    const int nTiles = K / BK;
    for (int kt = 0; kt < nTiles; ++kt) {
        const int cur = kt & 1, nxt = cur ^ 1;
        if (kt + 1 < nTiles) { loadA((kt + 1) * BK); loadB((kt + 1) * BK); }

#pragma unroll
        for (int kk = 0; kk < BK; ++kk) {
            unsigned long long a2[TM];
#pragma unroll
            for (int i = 0; i < TM; i += 2) {
                ulonglong2 t = *reinterpret_cast<const ulonglong2*>(
                    &As[cur][kk][ty * TM + i]);
                a2[i] = t.x; a2[i + 1] = t.y;
            }
            unsigned long long b2[TN / 2];
#pragma unroll
            for (int j = 0; j < TN / 4; ++j) {
                ulonglong2 bv = *reinterpret_cast<const ulonglong2*>(
                    &Bs[cur][kk][tx * TN + 4 * j]);
                b2[2 * j] = bv.x; b2[2 * j + 1] = bv.y;
            }
#pragma unroll
            for (int i = 0; i < TM; ++i)
#pragma unroll
                for (int j = 0; j < TN / 2; ++j) ffma2(acc[i][j], a2[i], b2[j]);
        }

        if (kt + 1 < nTiles) { storeA(nxt); storeB(nxt); }
        __syncthreads();
    }

#pragma unroll
    for (int i = 0; i < TM; ++i) {
        const int m = bm + ty * TM + i;
#pragma unroll
        for (int j = 0; j < TN / 2; ++j) {
            float lo, hi;
            unpack2(acc[i][j], lo, hi);
            float v[2] = {lo, hi};
            const int n0 = bn + tx * TN + 2 * j;
#pragma unroll
            for (int e = 0; e < 2; ++e) {
                const int n = n0 + e;
                if (n < N) {
                    float cv = v[e];
                    if (bias) cv += bias[n];
                    if (RELU) cv = fmaxf(cv, 0.0f);
                    C[(long)m * ldc + n] = cv;
                }
            }
        }
    }
}

// ---------------- threefry2x32 / JAX gumbel ----------------------------------
__device__ __forceinline__ float gumbel_at(uint32_t idx) {
    const uint32_t k0 = 0u, k1 = 42u;
    const uint32_t ks2 = k0 ^ k1 ^ 0x1BD11BDAu;
    uint32_t x0 = k0;
    uint32_t x1 = idx + k1;
#define RND(r) { x0 += x1; x1 = ((x1 << (r)) | (x1 >> (32 - (r)))) ^ x0; }
    RND(13) RND(15) RND(26) RND(6)   x0 += k1;  x1 += ks2 + 1u;
    RND(17) RND(29) RND(16) RND(24)  x0 += ks2; x1 += k0 + 2u;
    RND(13) RND(15) RND(26) RND(6)   x0 += k0;  x1 += k1 + 3u;
    RND(17) RND(29) RND(16) RND(24)  x0 += k1;  x1 += ks2 + 4u;
    RND(13) RND(15) RND(26) RND(6)   x0 += ks2; x1 += k0 + 5u;
#undef RND
    const uint32_t bits = x0 ^ x1;
    float f = __uint_as_float((bits >> 9) | 0x3f800000u) - 1.0f;
    float u = fmaxf(f, 1.17549435e-38f);
    return -logf(-logf(u));
}

// ---------------- softmax+sample, finalize -----------------------------------
__global__ void sample_kernel() {
    const int b = blockIdx.x;
    const float* __restrict__ row = g_logits + (long)b * A_;
    const int tid = threadIdx.x;
    __shared__ float sred[256];
    __shared__ int   sidx[256];

    float mx = -3.402823466e38f;
    for (int a = tid; a < A_; a += 256) mx = fmaxf(mx, row[a]);
    sred[tid] = mx; __syncthreads();
    for (int s = 128; s; s >>= 1) {
        if (tid < s) sred[tid] = fmaxf(sred[tid], sred[tid + s]);
        __syncthreads();
    }
    const float rmax = sred[0]; __syncthreads();

    float sum = 0.f;
    for (int a = tid; a < A_; a += 256) sum += expf(row[a] - rmax);
    sred[tid] = sum; __syncthreads();
    for (int s = 128; s; s >>= 1) {
        if (tid < s) sred[tid] += sred[tid + s];
        __syncthreads();
    }
    const float rsum = sred[0]; __syncthreads();

    float bestv = -3.402823466e38f;
    int   besti = A_;
    for (int a = tid; a < A_; a += 256) {
        float p = expf(row[a] - rmax) / rsum;
        float v = p + gumbel_at((uint32_t)(b * A_ + a));
        if (v > bestv) { bestv = v; besti = a; }
    }
    sred[tid] = bestv; sidx[tid] = besti; __syncthreads();
    for (int s = 128; s; s >>= 1) {
        if (tid < s) {
            float v2 = sred[tid + s]; int i2 = sidx[tid + s];
            if (v2 > sred[tid] || (v2 == sred[tid] && i2 < sidx[tid])) {
                sred[tid] = v2; sidx[tid] = i2;
            }
        }
        __syncthreads();
    }
    if (tid == 0) {
        const int a = sidx[0];
        g_action[b] = a;
        float p = expf(row[a] - rmax) / rsum;
        p = fminf(fmaxf(p, 1e-7f), 1.0f - 1e-7f);
        g_rowloss[b] = -logf(p);
    }
}

__global__ void finalize_kernel(float* __restrict__ out, int out_size) {
    const int tid = threadIdx.x;
    __shared__ float red[256];
    red[tid] = g_rowloss[tid];
    __syncthreads();
    for (int s = 128; s; s >>= 1) {
        if (tid < s) red[tid] += red[tid + s];
        __syncthreads();
    }
    const float loss = red[0] / (float)B_;

    if (out_size == 1) {
        if (tid == 0) out[0] = loss;
        return;
    }
    if (tid < B_ && tid < out_size) out[tid] = (float)g_action[tid];
    if (tid == 0 && out_size > B_) out[B_] = loss;
    for (int i = B_ + 1 + tid; i < out_size; i += 256) out[i] = 0.0f;
}

// ---------------- launch -----------------------------------------------------
extern "C" void kernel_launch(void* const* d_in, const int* in_sizes, int n_in,
                              void* d_out, int out_size) {
    const float* inputs = (const float*)d_in[0];
    const float* Wx     = (const float*)d_in[1];
    const float* Wh     = (const float*)d_in[2];
    const float* b_rnn  = (const float*)d_in[3];
    const float* W1     = (const float*)d_in[4];
    const float* b1     = (const float*)d_in[5];
    const float* W2     = (const float*)d_in[6];
    const float* b2     = (const float*)d_in[7];

    float *xw, *h, *hid, *logits;
    cudaGetSymbolAddress((void**)&xw,     g_xw);
    cudaGetSymbolAddress((void**)&h,      g_hbuf);
    cudaGetSymbolAddress((void**)&hid,    g_hid);
    cudaGetSymbolAddress((void**)&logits, g_logits);

    // xw = inputs @ Wx + b_rnn  — 3xTF32 tensor-core GEMM
    const int ga_smem = 8 * GA_TILE * 4;
    cudaFuncSetAttribute(gemm_a_mma,
                         cudaFuncAttributeMaxDynamicSharedMemorySize, ga_smem);
    gemm_a_mma<<<dim3(H_ / 128, (B_ * T_) / 128), 256, ga_smem>>>(
        inputs, Wx, b_rnn, xw);

    // persistent recurrence + fused dense1 — 3xTF32 mma
    const int smem = (int)sizeof(RecurSmem);   // 208896
    cudaFuncSetAttribute(rnn_recur, cudaFuncAttributeMaxDynamicSharedMemorySize, smem);
    rnn_recur<<<NBLK, RTHREADS, smem>>>(xw, Wh, W1, b1, h, hid);

    // logits = hid @ W2 + b2   (N=1000, ragged)
    sgemm_kernel<32, 64, 16, 4, 4, 128, false>
        <<<dim3((A_ + 63) / 64, B_ / 32), 128>>>(
            B_, A_, H_, hid, H_, W2, A_, b2, logits, A_);

    sample_kernel<<<B_, 256>>>();
    finalize_kernel<<<1, 256>>>((float*)d_out, out_size);
}